// round 7
// baseline (speedup 1.0000x reference)
#include <cuda_runtime.h>
#include <stdint.h>

#define NROWS   (64*2048)
#define DIM     64
#define KC      1024
#define QELEMS  (NROWS*DIM)
#define BT      256
#define CAP     8

// dynamic smem layout
#define SM_CB   0                    // int8 codebook, 1024*64 = 64 KB (uint4[KC*4])
#define SM_SL   (KC*DIM)             // float2 ssl1[KC] = 8 KB  (ss, L1w)
#define SM_WMX  (SM_SL + KC*8)       // float wmx[8]
#define SM_RED  (SM_WMX + 64)        // double sred[8]
#define SMEMSZ  (SM_RED + 64)

__device__ double g_loss_acc;

__global__ void vq_final(float* __restrict__ out){
    double m = g_loss_acc / (double)QELEMS;
    out[0] = (float)(m + 0.25*m);
    g_loss_acc = 0.0;          // reset for next replay (deterministic cycle)
}

// dp4a via PTX: signed int8x4 dot with s32 accumulate (unambiguous types)
static __device__ __forceinline__ int dp4a(int a, int b, int c){
    int r;
    asm("dp4a.s32.s32 %0, %1, %2, %3;" : "=r"(r) : "r"(a), "r"(b), "r"(c));
    return r;
}

// exact fp32 distance — replicates the round-1 (reference-matching) rounding order
static __device__ __forceinline__ float exact_dist(const float* __restrict__ wrow,
                                                   const float* __restrict__ xv, float cth){
    float ww[64];
    const float4* w4 = reinterpret_cast<const float4*>(wrow);
    #pragma unroll
    for (int i=0;i<16;i++){
        float4 v = w4[i];
        ww[4*i+0]=v.x; ww[4*i+1]=v.y; ww[4*i+2]=v.z; ww[4*i+3]=v.w;
    }
    float ss = 0.f;
    #pragma unroll
    for (int d=0; d<64; d++) ss = __fadd_rn(ss, __fmul_rn(ww[d], ww[d]));
    float s0=0.f, s1=0.f, s2=0.f, s3=0.f;
    #pragma unroll
    for (int d=0; d<64; d+=4){
        s0 = __fmaf_rn(xv[d+0], ww[d+0], s0);
        s1 = __fmaf_rn(xv[d+1], ww[d+1], s1);
        s2 = __fmaf_rn(xv[d+2], ww[d+2], s2);
        s3 = __fmaf_rn(xv[d+3], ww[d+3], s3);
    }
    float m = __fadd_rn(__fadd_rn(s0,s1), __fadd_rn(s2,s3));
    return __fsub_rn(__fadd_rn(cth, ss), __fmul_rn(2.0f, m));
}

static __device__ __forceinline__ int pack4(int a0,int a1,int a2,int a3){
    return (int)((uint32_t)(a0 & 0xFF) | ((uint32_t)(a1 & 0xFF) << 8)
         | ((uint32_t)(a2 & 0xFF) << 16) | ((uint32_t)(a3 & 0xFF) << 24));
}

__global__ __launch_bounds__(BT) void vq_main(const float* __restrict__ x,
                                              const float* __restrict__ w,
                                              float* __restrict__ out)
{
    extern __shared__ char sm[];
    int4*   cb   = reinterpret_cast<int4*>(sm + SM_CB);
    float2* ssl1 = reinterpret_cast<float2*>(sm + SM_SL);
    float*  wmx  = reinterpret_cast<float*>(sm + SM_WMX);
    double* sred = reinterpret_cast<double*>(sm + SM_RED);

    const int tid  = threadIdx.x;
    const int lane = tid & 31;
    const int warp = tid >> 5;
    const size_t row = (size_t)blockIdx.x*BT + tid;

    // ---- pass 1: global max|w| (block-local reduction) ----
    float wm = 0.f;
    {
        const float4* wg4 = reinterpret_cast<const float4*>(w);
        #pragma unroll 4
        for (int i = tid; i < KC*DIM/4; i += BT){
            float4 v = wg4[i];
            wm = fmaxf(wm, fmaxf(fmaxf(fabsf(v.x),fabsf(v.y)),
                                 fmaxf(fabsf(v.z),fabsf(v.w))));
        }
        #pragma unroll
        for (int o=16;o>0;o>>=1) wm = fmaxf(wm, __shfl_xor_sync(0xffffffffu, wm, o));
        if (lane == 0) wmx[warp] = wm;
    }
    __syncthreads();
    float wmax = wmx[0];
    #pragma unroll
    for (int i=1;i<BT/32;i++) wmax = fmaxf(wmax, wmx[i]);
    wmax = fmaxf(wmax, 1e-30f);
    const float sw    = 126.99f / wmax;
    const float invsw = wmax / 126.99f;

    // ---- x row stats (filter-grade) ----
    const float4* xr = reinterpret_cast<const float4*>(x + row*DIM);
    float maxr = 1e-30f, l1x = 0.f, s0=0.f,s1=0.f,s2=0.f,s3=0.f;
    #pragma unroll
    for (int i=0;i<16;i++){
        float4 v = xr[i];
        float ax=fabsf(v.x), ay=fabsf(v.y), az=fabsf(v.z), aw=fabsf(v.w);
        maxr = fmaxf(maxr, fmaxf(fmaxf(ax,ay), fmaxf(az,aw)));
        l1x += ((ax+ay)+(az+aw));
        s0 = __fmaf_rn(v.x,v.x,s0); s1 = __fmaf_rn(v.y,v.y,s1);
        s2 = __fmaf_rn(v.z,v.z,s2); s3 = __fmaf_rn(v.w,v.w,s3);
    }
    const float c4    = __fadd_rn(__fadd_rn(s0,s1), __fadd_rn(s2,s3));
    const float sx    = 126.99f / maxr;
    const float invsx = maxr / 126.99f;

    // ---- quantize x row into 16 packed int8x4 ----
    int xq[16];
    #pragma unroll
    for (int i=0;i<16;i++){
        float4 v = xr[i];
        xq[i] = pack4(__float2int_rn(v.x*sx), __float2int_rn(v.y*sx),
                      __float2int_rn(v.z*sx), __float2int_rn(v.w*sx));
    }

    // ---- pass 2: quantize codebook (4 codes per thread) + ss/L1 per code ----
    #pragma unroll
    for (int k=0;k<4;k++){
        int code = tid*4 + k;
        const float4* wr = reinterpret_cast<const float4*>(w + (size_t)code*DIM);
        float t0=0.f,t1=0.f,t2=0.f,t3=0.f, l1w=0.f;
        #pragma unroll
        for (int i=0;i<4;i++){
            int4 qv;
            int qq[4];
            #pragma unroll
            for (int j=0;j<4;j++){
                float4 v = wr[i*4+j];
                qq[j] = pack4(__float2int_rn(v.x*sw), __float2int_rn(v.y*sw),
                              __float2int_rn(v.z*sw), __float2int_rn(v.w*sw));
                t0 = __fmaf_rn(v.x,v.x,t0); t1 = __fmaf_rn(v.y,v.y,t1);
                t2 = __fmaf_rn(v.z,v.z,t2); t3 = __fmaf_rn(v.w,v.w,t3);
                l1w += ((fabsf(v.x)+fabsf(v.y))+(fabsf(v.z)+fabsf(v.w)));
            }
            qv.x=qq[0]; qv.y=qq[1]; qv.z=qq[2]; qv.w=qq[3];
            cb[code*4 + i] = qv;
        }
        ssl1[code] = make_float2(__fadd_rn(__fadd_rn(t0,t1),__fadd_rn(t2,t3)), l1w);
    }
    __syncthreads();

    // ---- main scan: 1024 codes, int8 dp4a + safe candidate window ----
    const float neg2r = -2.0f * (invsx * invsw);
    const float ebk1  = 1.25f * invsx;
    const float rowc  = __fmaf_rn(1.25f*invsw, l1x,
                         __fmaf_rn(40.f*invsw, invsx, 2e-4f));
    float U = 3.402823466e38f;
    int cnt = 0; bool ovf = false;
    unsigned short candI[CAP];
    float          candLo[CAP];

    #pragma unroll 2
    for (int code=0; code<KC; code++){
        const int4* cp = cb + code*4;
        int4 b0 = cp[0], b1 = cp[1], b2 = cp[2], b3 = cp[3];
        int d0=0,d1=0,d2=0,d3=0;
        d0 = dp4a(xq[0],  b0.x, d0); d1 = dp4a(xq[1],  b0.y, d1);
        d2 = dp4a(xq[2],  b0.z, d2); d3 = dp4a(xq[3],  b0.w, d3);
        d0 = dp4a(xq[4],  b1.x, d0); d1 = dp4a(xq[5],  b1.y, d1);
        d2 = dp4a(xq[6],  b1.z, d2); d3 = dp4a(xq[7],  b1.w, d3);
        d0 = dp4a(xq[8],  b2.x, d0); d1 = dp4a(xq[9],  b2.y, d1);
        d2 = dp4a(xq[10], b2.z, d2); d3 = dp4a(xq[11], b2.w, d3);
        d0 = dp4a(xq[12], b3.x, d0); d1 = dp4a(xq[13], b3.y, d1);
        d2 = dp4a(xq[14], b3.z, d2); d3 = dp4a(xq[15], b3.w, d3);
        int dot = (d0+d1)+(d2+d3);

        float2 sl = ssl1[code];
        float dva = __fmaf_rn((float)dot, neg2r, c4 + sl.x);
        float eb  = __fmaf_rn(ebk1, sl.y, rowc);
        float lo  = dva - eb;
        if (lo <= U){
            if (cnt == CAP){          // compact against current window
                int m = 0;
                #pragma unroll
                for (int t=0;t<CAP;t++){
                    if (candLo[t] <= U){ candLo[m]=candLo[t]; candI[m]=candI[t]; m++; }
                }
                cnt = m;
            }
            if (cnt < CAP){ candI[cnt] = (unsigned short)code; candLo[cnt] = lo; cnt++; }
            else ovf = true;
        }
        U = fminf(U, dva + eb);
    }

    // ---- exact recheck (ascending index, strict <  => first-min) ----
    float xv[64];
    #pragma unroll
    for (int i=0;i<16;i++){
        float4 v = xr[i];
        xv[4*i+0]=v.x; xv[4*i+1]=v.y; xv[4*i+2]=v.z; xv[4*i+3]=v.w;
    }
    float cth = 0.f;
    #pragma unroll
    for (int d=0; d<64; d++) cth = __fadd_rn(cth, __fmul_rn(xv[d], xv[d]));

    float minv = 3.402823466e38f; int mini = 0;
    if (!ovf){
        for (int k=0;k<cnt;k++){
            if (candLo[k] <= U){
                int idx = (int)candI[k];
                float d = exact_dist(w + (size_t)idx*DIM, xv, cth);
                if (d < minv){ minv = d; mini = idx; }
            }
        }
    } else {   // statistically unreachable safety net
        for (int idx=0; idx<KC; idx++){
            float d = exact_dist(w + (size_t)idx*DIM, xv, cth);
            if (d < minv){ minv = d; mini = idx; }
        }
    }

    // ---- outputs: index, straight-through row, loss partial ----
    out[1 + QELEMS + row] = (float)mini;
    {
        const float4* qw = reinterpret_cast<const float4*>(w + (size_t)mini*DIM);
        float stq[64];
        #pragma unroll
        for (int i=0;i<16;i++){
            float4 qv = qw[i];
            stq[4*i+0] = __fadd_rn(xv[4*i+0], __fsub_rn(qv.x, xv[4*i+0]));
            stq[4*i+1] = __fadd_rn(xv[4*i+1], __fsub_rn(qv.y, xv[4*i+1]));
            stq[4*i+2] = __fadd_rn(xv[4*i+2], __fsub_rn(qv.z, xv[4*i+2]));
            stq[4*i+3] = __fadd_rn(xv[4*i+3], __fsub_rn(qv.w, xv[4*i+3]));
        }
        // out+1 is only 4B-aligned: 3 scalars, 15 float4 (16B-aligned), 1 scalar
        float* og = out + 1 + row*DIM;
        og[0]=stq[0]; og[1]=stq[1]; og[2]=stq[2];
        float4* ov = reinterpret_cast<float4*>(og + 3);
        #pragma unroll
        for (int i=0;i<15;i++){
            float4 r;
            r.x=stq[3+4*i]; r.y=stq[4+4*i]; r.z=stq[5+4*i]; r.w=stq[6+4*i];
            ov[i] = r;
        }
        og[63]=stq[63];
    }

    double v = (double)minv;
    #pragma unroll
    for (int o=16;o>0;o>>=1) v += __shfl_down_sync(0xffffffffu, v, o);
    if (lane == 0) sred[warp] = v;
    __syncthreads();
    if (tid == 0){
        double s = 0.0;
        #pragma unroll
        for (int i=0;i<BT/32;i++) s += sred[i];
        atomicAdd(&g_loss_acc, s);
    }
}

extern "C" void kernel_launch(void* const* d_in, const int* in_sizes, int n_in,
                              void* d_out, int out_size)
{
    const float* x  = (const float*)d_in[0];
    const float* wt = (const float*)d_in[1];
    float* out = (float*)d_out;

    cudaFuncSetAttribute(vq_main, cudaFuncAttributeMaxDynamicSharedMemorySize, SMEMSZ);

    // 2-kernel cycle: g_loss_acc starts 0 (static init); vq_final resets it
    // after reading, so every graph replay sees a zeroed accumulator.
    vq_main<<<NROWS/BT, BT, SMEMSZ>>>(x, wt, out);
    vq_final<<<1,1>>>(out);
}

// round 8
// speedup vs baseline: 3.6347x; 3.6347x over previous
#include <cuda_runtime.h>
#include <stdint.h>

#define NROWS   (64*2048)
#define DIM     64
#define KC      1024
#define QELEMS  (NROWS*DIM)
#define BT      256
#define TILE    64
#define NTL     (KC/TILE)          // 16 tiles
#define TBYTES  (TILE*DIM*4)       // 16 KB per tile

__device__ double g_loss_acc;
__device__ int    g_ctr;

static __device__ __forceinline__ unsigned long long pack2(float a, float b){
    unsigned long long r;
    asm("mov.b64 %0, {%1,%2};" : "=l"(r) : "f"(a), "f"(b));
    return r;
}
static __device__ __forceinline__ void unpack2(unsigned long long v, float& a, float& b){
    asm("mov.b64 {%0,%1}, %2;" : "=f"(a), "=f"(b) : "l"(v));
}
static __device__ __forceinline__ unsigned long long ffma2(unsigned long long a,
                                                           unsigned long long b,
                                                           unsigned long long c){
    unsigned long long r;
    asm("fma.rn.f32x2 %0, %1, %2, %3;" : "=l"(r) : "l"(a), "l"(b), "l"(c));
    return r;
}
static __device__ __forceinline__ void cp16(uint32_t dst, const void* src){
    asm volatile("cp.async.cg.shared.global [%0], [%1], 16;" :: "r"(dst), "l"(src));
}

__global__ __launch_bounds__(BT, 2) void vq_main(const float* __restrict__ x,
                                                 const float* __restrict__ w,
                                                 float* __restrict__ out)
{
    __shared__ __align__(16) float sB[2][TILE*DIM];   // 32 KB double buffer
    __shared__ float  ssb[KC];                        // 4 KB code norms
    __shared__ double sred[BT/32];

    const int tid  = threadIdx.x;
    const int lane = tid & 31;
    const int warp = tid >> 5;
    const size_t row = (size_t)blockIdx.x*BT + tid;

    const uint32_t sb0 = (uint32_t)__cvta_generic_to_shared(&sB[0][0]);

    // ---- prologue: async-load tile 0 (codes 0..63) ----
    {
        const char* src = (const char*)w + (size_t)tid*16;
        uint32_t dst = sb0 + tid*16;
        #pragma unroll
        for (int i=0;i<TBYTES/(BT*16);i++)           // 4 x 16B per thread
            cp16(dst + i*BT*16, src + i*BT*16);
        asm volatile("cp.async.commit_group;");
    }

    // ---- codebook norms once per block, reference-sequential order ----
    #pragma unroll
    for (int k=0;k<KC/BT;k++){                       // 4 codes per thread
        int code = tid*(KC/BT) + k;
        const float4* wr = reinterpret_cast<const float4*>(w + (size_t)code*DIM);
        float s = 0.f;
        #pragma unroll
        for (int i=0;i<16;i++){
            float4 v = wr[i];
            s = __fadd_rn(s, __fmul_rn(v.x,v.x));
            s = __fadd_rn(s, __fmul_rn(v.y,v.y));
            s = __fadd_rn(s, __fmul_rn(v.z,v.z));
            s = __fadd_rn(s, __fmul_rn(v.w,v.w));
        }
        ssb[code] = s;
    }

    // ---- this thread's row: packed pairs + sequential ||x||^2 ----
    unsigned long long xp[DIM/2];
    float c4 = 0.f;
    {
        const float4* xr = reinterpret_cast<const float4*>(x + row*DIM);
        #pragma unroll
        for (int i=0;i<16;i++){
            float4 v = xr[i];
            c4 = __fadd_rn(c4, __fmul_rn(v.x,v.x));
            c4 = __fadd_rn(c4, __fmul_rn(v.y,v.y));
            c4 = __fadd_rn(c4, __fmul_rn(v.z,v.z));
            c4 = __fadd_rn(c4, __fmul_rn(v.w,v.w));
            xp[2*i]   = pack2(v.x, v.y);
            xp[2*i+1] = pack2(v.z, v.w);
        }
    }

    const unsigned long long one2 = pack2(1.0f, 1.0f);
    float minv = 3.402823466e38f;
    int   mini = 0;

    // ---- main loop: 16 tiles x 64 codes, FFMA2 on 4 chains ----
    #pragma unroll 1
    for (int t=0; t<NTL; t++){
        if (t+1 < NTL){
            const char* src = (const char*)w + (size_t)(t+1)*TBYTES + tid*16;
            uint32_t dst = sb0 + (uint32_t)(((t+1)&1)*TBYTES) + tid*16;
            #pragma unroll
            for (int i=0;i<TBYTES/(BT*16);i++)
                cp16(dst + i*BT*16, src + i*BT*16);
            asm volatile("cp.async.commit_group;");
            asm volatile("cp.async.wait_group 1;");  // tile t complete
        } else {
            asm volatile("cp.async.wait_group 0;");
        }
        __syncthreads();

        const uint32_t tb = sb0 + (uint32_t)((t&1)*TBYTES);
        const int cbase = t*TILE;
        #pragma unroll 2
        for (int c=0;c<TILE;c++){
            uint32_t addr = tb + (uint32_t)c*(DIM*4);
            unsigned long long a0=0ull,a1=0ull,a2=0ull,a3=0ull;
            #pragma unroll
            for (int j=0;j<8;j++){
                unsigned long long e0,e1,e2,e3;
                asm volatile("ld.shared.v2.u64 {%0,%1}, [%2];"
                             : "=l"(e0),"=l"(e1) : "r"(addr + j*32));
                asm volatile("ld.shared.v2.u64 {%0,%1}, [%2];"
                             : "=l"(e2),"=l"(e3) : "r"(addr + j*32 + 16));
                a0 = ffma2(xp[4*j+0], e0, a0);
                a1 = ffma2(xp[4*j+1], e1, a1);
                a2 = ffma2(xp[4*j+2], e2, a2);
                a3 = ffma2(xp[4*j+3], e3, a3);
            }
            unsigned long long mp =
                ffma2(ffma2(a3, one2, a2), one2, ffma2(a1, one2, a0));
            float mlo, mhi; unpack2(mp, mlo, mhi);
            float m  = __fadd_rn(mlo, mhi);
            // dist = (c4+ss) - 2m;  2m exact so FMA == fsub(fadd, 2m) bitwise
            float dv = __fmaf_rn(m, -2.0f, __fadd_rn(c4, ssb[cbase + c]));
            if (dv < minv){ minv = dv; mini = cbase + c; }   // first-min
        }
        __syncthreads();   // protect buf (t&1) before tile t+2 prefetch
    }

    // ---- outputs: index, straight-through row (scalar stores), loss ----
    out[1 + QELEMS + row] = (float)mini;
    {
        const float4* qw = reinterpret_cast<const float4*>(w + (size_t)mini*DIM);
        float* og = out + 1 + row*DIM;
        #pragma unroll
        for (int i=0;i<16;i++){
            float4 qv = qw[i];
            float x0,x1,x2,x3;
            unpack2(xp[2*i],   x0, x1);
            unpack2(xp[2*i+1], x2, x3);
            og[4*i+0] = __fadd_rn(x0, __fsub_rn(qv.x, x0));
            og[4*i+1] = __fadd_rn(x1, __fsub_rn(qv.y, x1));
            og[4*i+2] = __fadd_rn(x2, __fsub_rn(qv.z, x2));
            og[4*i+3] = __fadd_rn(x3, __fsub_rn(qv.w, x3));
        }
    }

    double v = (double)minv;
    #pragma unroll
    for (int o=16;o>0;o>>=1) v += __shfl_down_sync(0xffffffffu, v, o);
    if (lane == 0) sred[warp] = v;
    __syncthreads();
    if (tid == 0){
        double s = 0.0;
        #pragma unroll
        for (int i=0;i<BT/32;i++) s += sred[i];
        atomicAdd(&g_loss_acc, s);
        __threadfence();
        int done = atomicAdd(&g_ctr, 1);
        if (done == (int)gridDim.x - 1){
            double tot = atomicAdd(&g_loss_acc, 0.0);      // coherent read
            out[0] = (float)(tot*1.25/(double)QELEMS);     // /2^23 exact
            g_ctr = 0;                                     // reset for replay
            g_loss_acc = 0.0;
        }
    }
}

extern "C" void kernel_launch(void* const* d_in, const int* in_sizes, int n_in,
                              void* d_out, int out_size)
{
    const float* x  = (const float*)d_in[0];
    const float* wt = (const float*)d_in[1];
    float* out = (float*)d_out;
    vq_main<<<NROWS/BT, BT>>>(x, wt, out);
}

// round 9
// speedup vs baseline: 4.0273x; 1.1080x over previous
#include <cuda_runtime.h>
#include <stdint.h>

#define NROWS   (64*2048)
#define DIM     64
#define KC      1024
#define QELEMS  (NROWS*DIM)
#define BT      256
#define RPB     (BT*2)             // 512 rows? no: 2 rows per lane-PAIR => BT rows... see below
#define TILE    64
#define NTL     (KC/TILE)          // 16 tiles
#define TBYTES  (TILE*DIM*4)       // 16 KB per tile

// rows per block = (BT/2 pairs) * 2 rows = BT = 256 rows
#define ROWSPB  BT

__device__ double g_loss_acc;
__device__ int    g_ctr;

static __device__ __forceinline__ unsigned long long pack2(float a, float b){
    unsigned long long r;
    asm("mov.b64 %0, {%1,%2};" : "=l"(r) : "f"(a), "f"(b));
    return r;
}
static __device__ __forceinline__ void unpack2(unsigned long long v, float& a, float& b){
    asm("mov.b64 {%0,%1}, %2;" : "=f"(a), "=f"(b) : "l"(v));
}
static __device__ __forceinline__ unsigned long long ffma2(unsigned long long a,
                                                           unsigned long long b,
                                                           unsigned long long c){
    unsigned long long r;
    asm("fma.rn.f32x2 %0, %1, %2, %3;" : "=l"(r) : "l"(a), "l"(b), "l"(c));
    return r;
}
static __device__ __forceinline__ void cp16(uint32_t dst, const void* src){
    asm volatile("cp.async.cg.shared.global [%0], [%1], 16;" :: "r"(dst), "l"(src));
}

// B tile smem layout: code c, 16B-chunk g (g=0..15, dims 4g..4g+3):
//   offset = c*256 + (g&7)*32 + (g>>3)*16
// => per code, half h sits at c*256 + j*32 + h*16 (j=0..7): even/odd lanes
//    read adjacent 16B chunks -> single conflict-free wavefront.
static __device__ __forceinline__ uint32_t bmap(int G){   // G = c*16+g within tile
    int c = G >> 4, g = G & 15;
    return (uint32_t)(c*256 + (g&7)*32 + (g>>3)*16);
}

__global__ __launch_bounds__(BT, 2) void vq_main(const float* __restrict__ x,
                                                 const float* __restrict__ w,
                                                 float* __restrict__ out)
{
    __shared__ __align__(16) float sB[2][TILE*DIM];   // 32 KB double buffer
    __shared__ float  ssb[KC];                        // 4 KB code norms
    __shared__ double sred[BT/32];

    const int tid  = threadIdx.x;
    const int lane = tid & 31;
    const int warp = tid >> 5;
    const int h    = tid & 1;            // half: 0 -> dims 0..31, 1 -> dims 32..63
    const int p    = tid >> 1;           // pair id
    const size_t base = (size_t)blockIdx.x * ROWSPB;
    const size_t rA   = base + 2*p;      // even lane owns rA
    const size_t rOwn = rA + h;          // this lane's owned row

    const uint32_t sb0 = (uint32_t)__cvta_generic_to_shared(&sB[0][0]);

    // ---- prologue: async-load tile 0 with half-interleaved layout ----
    #pragma unroll
    for (int i=0;i<TBYTES/(BT*16);i++){
        int G = tid + i*BT;
        cp16(sb0 + bmap(G), (const char*)w + (size_t)G*16);
    }
    asm volatile("cp.async.commit_group;");

    // ---- codebook norms once per block, reference-sequential order ----
    #pragma unroll
    for (int k=0;k<KC/BT;k++){
        int code = tid*(KC/BT) + k;
        const float4* wr = reinterpret_cast<const float4*>(w + (size_t)code*DIM);
        float s = 0.f;
        #pragma unroll
        for (int i=0;i<16;i++){
            float4 v = wr[i];
            s = __fadd_rn(s, __fmul_rn(v.x,v.x));
            s = __fadd_rn(s, __fmul_rn(v.y,v.y));
            s = __fadd_rn(s, __fmul_rn(v.z,v.z));
            s = __fadd_rn(s, __fmul_rn(v.w,v.w));
        }
        ssb[code] = s;
    }

    // ---- register x: half h of rows rA and rA+1 (16 f32x2 each) ----
    unsigned long long xpA[16], xpB[16];
    {
        const float4* a4 = reinterpret_cast<const float4*>(x + rA*DIM + h*32);
        const float4* b4 = reinterpret_cast<const float4*>(x + (rA+1)*DIM + h*32);
        #pragma unroll
        for (int i=0;i<8;i++){
            float4 va = a4[i], vb = b4[i];
            xpA[2*i]   = pack2(va.x, va.y);
            xpA[2*i+1] = pack2(va.z, va.w);
            xpB[2*i]   = pack2(vb.x, vb.y);
            xpB[2*i+1] = pack2(vb.z, vb.w);
        }
    }
    // ---- exact sequential ||x||^2 of the OWNED row ----
    float c4 = 0.f;
    {
        const float4* xr = reinterpret_cast<const float4*>(x + rOwn*DIM);
        #pragma unroll
        for (int i=0;i<16;i++){
            float4 v = xr[i];
            c4 = __fadd_rn(c4, __fmul_rn(v.x,v.x));
            c4 = __fadd_rn(c4, __fmul_rn(v.y,v.y));
            c4 = __fadd_rn(c4, __fmul_rn(v.z,v.z));
            c4 = __fadd_rn(c4, __fmul_rn(v.w,v.w));
        }
    }

    const unsigned long long one2 = pack2(1.0f, 1.0f);
    float minv = 3.402823466e38f;
    int   mini = 0;

    // ---- main loop: 16 tiles x 64 codes ----
    #pragma unroll 1
    for (int t=0; t<NTL; t++){
        if (t+1 < NTL){
            const char* srcb = (const char*)w + (size_t)(t+1)*TBYTES;
            uint32_t dstb = sb0 + (uint32_t)(((t+1)&1)*TBYTES);
            #pragma unroll
            for (int i=0;i<TBYTES/(BT*16);i++){
                int G = tid + i*BT;
                cp16(dstb + bmap(G), srcb + (size_t)G*16);
            }
            asm volatile("cp.async.commit_group;");
            asm volatile("cp.async.wait_group 1;");
        } else {
            asm volatile("cp.async.wait_group 0;");
        }
        __syncthreads();

        const uint32_t tb = sb0 + (uint32_t)((t&1)*TBYTES) + (uint32_t)(h*16);
        const int cbase = t*TILE;
        #pragma unroll 2
        for (int c=0;c<TILE;c++){
            uint32_t addr = tb + (uint32_t)c*256;
            unsigned long long aA0=0ull,aA1=0ull,aB0=0ull,aB1=0ull;
            #pragma unroll
            for (int j=0;j<8;j++){
                unsigned long long e0,e1;
                asm volatile("ld.shared.v2.u64 {%0,%1}, [%2];"
                             : "=l"(e0),"=l"(e1) : "r"(addr + j*32));
                aA0 = ffma2(xpA[2*j],   e0, aA0);
                aA1 = ffma2(xpA[2*j+1], e1, aA1);
                aB0 = ffma2(xpB[2*j],   e0, aB0);
                aB1 = ffma2(xpB[2*j+1], e1, aB1);
            }
            float alo,ahi,blo,bhi;
            unpack2(ffma2(aA1, one2, aA0), alo, ahi);
            unpack2(ffma2(aB1, one2, aB0), blo, bhi);
            float msA = __fadd_rn(alo, ahi);        // my half-dot, row A
            float msB = __fadd_rn(blo, bhi);        // my half-dot, row B
            // exchange: send partner the half it needs for ITS owned row
            float v   = h ? msA : msB;
            float own = h ? msB : msA;
            float vr  = __shfl_xor_sync(0xffffffffu, v, 1);
            float m   = __fadd_rn(own, vr);         // full dot of owned row
            float dv  = __fmaf_rn(m, -2.0f, __fadd_rn(c4, ssb[cbase + c]));
            if (dv < minv){ minv = dv; mini = cbase + c; }   // first-min
        }
        __syncthreads();
    }

    // ---- outputs: every lane owns exactly one row ----
    out[1 + QELEMS + rOwn] = (float)mini;
    {
        const float4* qw = reinterpret_cast<const float4*>(w + (size_t)mini*DIM);
        const float4* xr = reinterpret_cast<const float4*>(x + rOwn*DIM);
        float stq[64];
        #pragma unroll
        for (int i=0;i<16;i++){
            float4 qv = qw[i];
            float4 xv = xr[i];
            stq[4*i+0] = __fadd_rn(xv.x, __fsub_rn(qv.x, xv.x));
            stq[4*i+1] = __fadd_rn(xv.y, __fsub_rn(qv.y, xv.y));
            stq[4*i+2] = __fadd_rn(xv.z, __fsub_rn(qv.z, xv.z));
            stq[4*i+3] = __fadd_rn(xv.w, __fsub_rn(qv.w, xv.w));
        }
        // out+1 is 4B-aligned only: 3 scalars, 15 float4, 1 scalar
        float* og = out + 1 + rOwn*DIM;
        og[0]=stq[0]; og[1]=stq[1]; og[2]=stq[2];
        float4* ov = reinterpret_cast<float4*>(og + 3);
        #pragma unroll
        for (int i=0;i<15;i++){
            float4 r;
            r.x=stq[3+4*i]; r.y=stq[4+4*i]; r.z=stq[5+4*i]; r.w=stq[6+4*i];
            ov[i] = r;
        }
        og[63]=stq[63];
    }

    // ---- fp64 loss reduction + fused finalize ----
    double vsum = (double)minv;
    #pragma unroll
    for (int o=16;o>0;o>>=1) vsum += __shfl_down_sync(0xffffffffu, vsum, o);
    if (lane == 0) sred[warp] = vsum;
    __syncthreads();
    if (tid == 0){
        double s = 0.0;
        #pragma unroll
        for (int i=0;i<BT/32;i++) s += sred[i];
        atomicAdd(&g_loss_acc, s);
        __threadfence();
        int done = atomicAdd(&g_ctr, 1);
        if (done == (int)gridDim.x - 1){
            double tot = atomicAdd(&g_loss_acc, 0.0);
            out[0] = (float)(tot*1.25/(double)QELEMS);
            g_ctr = 0;
            g_loss_acc = 0.0;
        }
    }
}

extern "C" void kernel_launch(void* const* d_in, const int* in_sizes, int n_in,
                              void* d_out, int out_size)
{
    const float* x  = (const float*)d_in[0];
    const float* wt = (const float*)d_in[1];
    float* out = (float*)d_out;
    vq_main<<<NROWS/ROWSPB, BT>>>(x, wt, out);
}